// round 5
// baseline (speedup 1.0000x reference)
#include <cuda_runtime.h>

// 2-layer GCN, atomic-free feature aggregation via device-built CSR.
// h  = relu(Anorm(x @ W1) + b1)
// out= relu(Anorm(h @ W2) + b2)
// Anorm: add self-loops, symmetric normalization by in-degree rsqrt.
//
// edge_index dtype (int32 vs int64) is detected at runtime.

#define NODES 100000
#define EMAX  1600000
#define KIN   128
#define SCAN_BLK 256
#define NBLK ((NODES + SCAN_BLK - 1) / SCAN_BLK)   // 391

// ---------------- device scratch ------------------------------------------
__device__ int    g_is64;
__device__ int    g_src[EMAX];
__device__ int    g_dst[EMAX];
__device__ int    g_cnt[NODES];        // in-degree (excl self-loop)
__device__ int    g_rs_local[NODES];
__device__ int    g_partial[NBLK];
__device__ int    g_blockoff[NBLK];
__device__ int    g_row_start[NODES];
__device__ int    g_cursor[NODES];
__device__ int    g_eidx[EMAX];        // CSR: src indices grouped by dst
__device__ float  g_dinv[NODES];
__device__ float4 g_h1[(size_t)NODES * 32];  // x @ W1            [N,128]
__device__ float4 g_a1[(size_t)NODES * 32];  // aggregated layer1 [N,128]
__device__ float2 g_h2[(size_t)NODES * 32];  // relu(a1+b1) @ W2  [N,64]

// ---------------- edge dtype detect + convert ------------------------------
// int64 little-endian with values < 100000 => every odd 32-bit word is 0.
__global__ void detect_k(const int* __restrict__ raw) {
    int zc = 0;
    for (int i = threadIdx.x; i < 1024; i += 32)
        if (raw[2 * i + 1] == 0) zc++;
#pragma unroll
    for (int o = 16; o > 0; o >>= 1)
        zc += __shfl_down_sync(0xffffffffu, zc, o);
    if (threadIdx.x == 0) g_is64 = (zc > 512) ? 1 : 0;
}

__global__ void convert_k(const int* __restrict__ raw, int E) {
    int e = blockIdx.x * blockDim.x + threadIdx.x;
    if (e >= E) return;
    if (g_is64) {
        g_src[e] = raw[2 * e];            // low word of int64 src[e]
        g_dst[e] = raw[2 * (E + e)];      // low word of int64 dst[e]
    } else {
        g_src[e] = raw[e];
        g_dst[e] = raw[E + e];
    }
}

// ---------------- CSR build ------------------------------------------------
__global__ void cnt_init_k() {
    int i = blockIdx.x * blockDim.x + threadIdx.x;
    if (i < NODES) g_cnt[i] = 0;
}

__global__ void cnt_count_k(int E) {
    int e = blockIdx.x * blockDim.x + threadIdx.x;
    if (e >= E) return;
    unsigned d = (unsigned)g_dst[e];
    if (d < NODES) atomicAdd(&g_cnt[d], 1);   // guard: wrong answer > trap
}

__global__ void dinv_k() {
    int i = blockIdx.x * blockDim.x + threadIdx.x;
    if (i < NODES) g_dinv[i] = rsqrtf(1.0f + (float)g_cnt[i]);
}

// pass 1: per-block inclusive scan; emit block-local exclusive + block totals
__global__ void scan1_k() {
    __shared__ int sh[SCAN_BLK];
    int tid = threadIdx.x;
    int i = blockIdx.x * SCAN_BLK + tid;
    int c = (i < NODES) ? g_cnt[i] : 0;
    sh[tid] = c;
    __syncthreads();
#pragma unroll
    for (int ofs = 1; ofs < SCAN_BLK; ofs <<= 1) {
        int v = (tid >= ofs) ? sh[tid - ofs] : 0;
        __syncthreads();
        sh[tid] += v;
        __syncthreads();
    }
    if (i < NODES) g_rs_local[i] = sh[tid] - c;
    if (tid == SCAN_BLK - 1) g_partial[blockIdx.x] = sh[tid];
}

// pass 2: single block scans the NBLK partials (exclusive)
__global__ void scan2_k() {
    __shared__ int sh[512];
    int tid = threadIdx.x;
    int c = (tid < NBLK) ? g_partial[tid] : 0;
    sh[tid] = c;
    __syncthreads();
#pragma unroll
    for (int ofs = 1; ofs < 512; ofs <<= 1) {
        int v = (tid >= ofs) ? sh[tid - ofs] : 0;
        __syncthreads();
        sh[tid] += v;
        __syncthreads();
    }
    if (tid < NBLK) g_blockoff[tid] = sh[tid] - c;
}

// pass 3: global row_start + cursor init
__global__ void scan3_k() {
    int i = blockIdx.x * blockDim.x + threadIdx.x;
    if (i >= NODES) return;
    int rs = g_rs_local[i] + g_blockoff[i / SCAN_BLK];
    g_row_start[i] = rs;
    g_cursor[i]    = rs;
}

__global__ void place_k(int E) {
    int e = blockIdx.x * blockDim.x + threadIdx.x;
    if (e >= E) return;
    unsigned d = (unsigned)g_dst[e];
    unsigned s = (unsigned)g_src[e];
    if (d < NODES && s < NODES) {
        int p = atomicAdd(&g_cursor[d], 1);
        g_eidx[p] = (int)s;
    }
}

// ---------------- SGEMM: C[M,BN] = A[M,128] @ W[128,BN] -------------------
// 128 x BN tile, 256 threads, 8 x (BN/16) register microtile.
// LAYER2: A := relu(g_a1 + bias[k]), C := g_h2. else: A := x, C := g_h1.
template <int BN, bool LAYER2>
__global__ void __launch_bounds__(256) sgemm_k(
    const float* __restrict__ Ain, const float* __restrict__ W,
    const float* __restrict__ bias, int M)
{
    constexpr int BM = 128, BK = 8, K = KIN;
    constexpr int TN = BN / 16;

    const float* __restrict__ A = LAYER2 ? (const float*)g_a1 : Ain;
    float* __restrict__ C = LAYER2 ? (float*)g_h2 : (float*)g_h1;

    __shared__ float As[BK][BM];
    __shared__ float Ws[BK][BN];

    const int tid = threadIdx.x;
    const int tx = tid & 15;
    const int ty = tid >> 4;
    const int row0 = blockIdx.x * BM;

    float acc[8][TN];
#pragma unroll
    for (int i = 0; i < 8; i++)
#pragma unroll
        for (int j = 0; j < TN; j++) acc[i][j] = 0.0f;

    const int arow = tid >> 1;
    const int akq  = (tid & 1) * 4;

    constexpr int WLOADS = BK * BN / 4;
    const int wr = (tid * 4) / BN;
    const int wc = (tid * 4) % BN;

    for (int k0 = 0; k0 < K; k0 += BK) {
        float4 av = make_float4(0.f, 0.f, 0.f, 0.f);
        const int gr = row0 + arow;
        if (gr < M)
            av = *(const float4*)(A + (size_t)gr * K + k0 + akq);
        if (LAYER2) {
            const float4 bv = *(const float4*)(bias + k0 + akq);
            av.x = fmaxf(av.x + bv.x, 0.f);
            av.y = fmaxf(av.y + bv.y, 0.f);
            av.z = fmaxf(av.z + bv.z, 0.f);
            av.w = fmaxf(av.w + bv.w, 0.f);
        }
        As[akq + 0][arow] = av.x;
        As[akq + 1][arow] = av.y;
        As[akq + 2][arow] = av.z;
        As[akq + 3][arow] = av.w;

        if (tid < WLOADS) {
            const float4 wv = *(const float4*)(W + (size_t)(k0 + wr) * BN + wc);
            Ws[wr][wc + 0] = wv.x;
            Ws[wr][wc + 1] = wv.y;
            Ws[wr][wc + 2] = wv.z;
            Ws[wr][wc + 3] = wv.w;
        }
        __syncthreads();

#pragma unroll
        for (int k = 0; k < BK; k++) {
            float a[8], b[TN];
#pragma unroll
            for (int i = 0; i < 8; i++) a[i] = As[k][ty * 8 + i];
#pragma unroll
            for (int j = 0; j < TN; j++) b[j] = Ws[k][tx * TN + j];
#pragma unroll
            for (int i = 0; i < 8; i++)
#pragma unroll
                for (int j = 0; j < TN; j++) acc[i][j] += a[i] * b[j];
        }
        __syncthreads();
    }

#pragma unroll
    for (int i = 0; i < 8; i++) {
        const int gr = row0 + ty * 8 + i;
        if (gr < M) {
#pragma unroll
            for (int j = 0; j < TN; j += 4) {
                float4 v = make_float4(acc[i][j], acc[i][j+1], acc[i][j+2], acc[i][j+3]);
                *(float4*)(C + (size_t)gr * BN + tx * TN + j) = v;
            }
        }
    }
}

// ---------------- gather aggregation (atomic-free) -------------------------
// layer1: warp per node, lane owns one float4 (128 floats/row).
__global__ void __launch_bounds__(256) agg1_k() {
    int w    = (blockIdx.x * blockDim.x + threadIdx.x) >> 5;
    int lane = threadIdx.x & 31;
    if (w >= NODES) return;

    float dd = g_dinv[w];
    float4 acc = g_h1[(size_t)w * 32 + lane];
    float s2 = dd * dd;
    acc.x *= s2; acc.y *= s2; acc.z *= s2; acc.w *= s2;

    const int n  = g_cnt[w];
    const int rs = g_row_start[w];

    for (int base = 0; base < n; base += 32) {
        int m = n - base; if (m > 32) m = 32;
        int   si = 0; float nd = 0.f;
        if (lane < m) {
            si = g_eidx[rs + base + lane];
            nd = g_dinv[si] * dd;
        }
        for (int j = 0; j < m; j++) {
            int   ss = __shfl_sync(0xffffffffu, si, j);
            float nn = __shfl_sync(0xffffffffu, nd, j);
            float4 v = g_h1[(size_t)ss * 32 + lane];
            acc.x += v.x * nn; acc.y += v.y * nn;
            acc.z += v.z * nn; acc.w += v.w * nn;
        }
    }
    g_a1[(size_t)w * 32 + lane] = acc;
}

// layer2: warp per node, lane owns one float2 (64 floats/row).
// Fuses self-loop init AND final bias+relu; writes d_out directly.
__global__ void __launch_bounds__(256) agg2_k(float2* __restrict__ out,
                                              const float2* __restrict__ b2) {
    int w    = (blockIdx.x * blockDim.x + threadIdx.x) >> 5;
    int lane = threadIdx.x & 31;
    if (w >= NODES) return;

    float dd = g_dinv[w];
    float2 acc = g_h2[(size_t)w * 32 + lane];
    float s2 = dd * dd;
    acc.x *= s2; acc.y *= s2;

    const int n  = g_cnt[w];
    const int rs = g_row_start[w];

    for (int base = 0; base < n; base += 32) {
        int m = n - base; if (m > 32) m = 32;
        int   si = 0; float nd = 0.f;
        if (lane < m) {
            si = g_eidx[rs + base + lane];
            nd = g_dinv[si] * dd;
        }
        for (int j = 0; j < m; j++) {
            int   ss = __shfl_sync(0xffffffffu, si, j);
            float nn = __shfl_sync(0xffffffffu, nd, j);
            float2 v = g_h2[(size_t)ss * 32 + lane];
            acc.x += v.x * nn; acc.y += v.y * nn;
        }
    }
    float2 b = b2[lane];
    acc.x = fmaxf(acc.x + b.x, 0.f);
    acc.y = fmaxf(acc.y + b.y, 0.f);
    out[(size_t)w * 32 + lane] = acc;
}

// ---------------- launch ---------------------------------------------------
extern "C" void kernel_launch(void* const* d_in, const int* in_sizes, int n_in,
                              void* d_out, int out_size) {
    // Identify inputs by element count (all six are unique); fall back to
    // positional order (x, edge_index, W1, b1, W2, b2) if a size is missing.
    const float* x  = (const float*)d_in[0];
    const void*  ei = d_in[1];
    const float* W1 = (const float*)d_in[2];
    const float* b1 = (const float*)d_in[3];
    const float* W2 = (const float*)d_in[4];
    const float* b2 = (const float*)d_in[5];
    int E = in_sizes[1] / 2;

    for (int i = 0; i < n_in; i++) {
        switch (in_sizes[i]) {
            case NODES * KIN:   x  = (const float*)d_in[i]; break;   // 12.8M
            case 2 * EMAX:      ei = d_in[i]; E = in_sizes[i] / 2; break; // 3.2M
            case KIN * 128:     W1 = (const float*)d_in[i]; break;   // 16384
            case 128:           b1 = (const float*)d_in[i]; break;
            case 128 * 64:      W2 = (const float*)d_in[i]; break;   // 8192
            case 64:            b2 = (const float*)d_in[i]; break;
            default: break;
        }
    }
    if (E > EMAX) E = EMAX;

    const int M = NODES;
    const int gemm_blocks = (M + 127) / 128;
    const int node_blocks = (NODES + 255) / 256;
    const int edge_blocks = (E + 255) / 256;
    const int warp_blocks = (NODES * 32 + 255) / 256;  // warp per node

    detect_k  <<<1, 32>>>((const int*)ei);
    convert_k <<<edge_blocks, 256>>>((const int*)ei, E);

    cnt_init_k <<<node_blocks, 256>>>();
    cnt_count_k<<<edge_blocks, 256>>>(E);
    dinv_k     <<<node_blocks, 256>>>();
    scan1_k    <<<NBLK, SCAN_BLK>>>();
    scan2_k    <<<1, 512>>>();
    scan3_k    <<<node_blocks, 256>>>();
    place_k    <<<edge_blocks, 256>>>(E);

    sgemm_k<128, false><<<gemm_blocks, 256>>>(x, W1, nullptr, M);
    agg1_k<<<warp_blocks, 256>>>();

    sgemm_k<64, true><<<gemm_blocks, 256>>>(nullptr, W2, b1, M);
    agg2_k<<<warp_blocks, 256>>>((float2*)d_out, (const float2*)b2);
}

// round 6
// speedup vs baseline: 1.0674x; 1.0674x over previous
#include <cuda_runtime.h>
#include <cstdint>

// 2-layer GCN, atomic-free aggregation via device-built CSR.
// GEMMs on tensor cores (mma.sync tf32), fp32 accumulate.
// h  = relu(Anorm(x @ W1) + b1);  out = relu(Anorm(h @ W2) + b2)

#define NODES 100000
#define EMAX  1600000
#define KIN   128
#define SCAN_BLK 256
#define NBLK ((NODES + SCAN_BLK - 1) / SCAN_BLK)   // 391

// ---------------- device scratch ------------------------------------------
__device__ int    g_is64;
__device__ int    g_cnt[NODES];        // in-degree (excl self-loop)
__device__ int    g_rs_local[NODES];
__device__ int    g_partial[NBLK];
__device__ int    g_blockoff[NBLK];
__device__ int    g_row_start[NODES];
__device__ int    g_cursor[NODES];
__device__ int    g_eidx[EMAX];        // CSR: src indices grouped by dst
__device__ float  g_dinv[NODES];
__device__ float4 g_h1[(size_t)NODES * 32];  // x @ W1            [N,128]
__device__ float4 g_a1[(size_t)NODES * 32];  // aggregated layer1 [N,128]
__device__ float2 g_h2[(size_t)NODES * 32];  // relu(a1+b1) @ W2  [N,64]

// ---------------- edge dtype detect ----------------------------------------
// int64 little-endian with values < 100000 => every odd 32-bit word is 0.
__global__ void detect_k(const int* __restrict__ raw) {
    int zc = 0;
    for (int i = threadIdx.x; i < 1024; i += 32)
        if (raw[2 * i + 1] == 0) zc++;
#pragma unroll
    for (int o = 16; o > 0; o >>= 1)
        zc += __shfl_down_sync(0xffffffffu, zc, o);
    if (threadIdx.x == 0) g_is64 = (zc > 512) ? 1 : 0;
}

__device__ __forceinline__ int edge_src(const int* raw, int E, int e) {
    return g_is64 ? raw[2 * e] : raw[e];
}
__device__ __forceinline__ int edge_dst(const int* raw, int E, int e) {
    return g_is64 ? raw[2 * (E + e)] : raw[E + e];
}

// ---------------- CSR build ------------------------------------------------
__global__ void cnt_init_k() {
    int i = blockIdx.x * blockDim.x + threadIdx.x;
    if (i < NODES) g_cnt[i] = 0;
}

__global__ void cnt_count_k(const int* __restrict__ raw, int E) {
    int e = blockIdx.x * blockDim.x + threadIdx.x;
    if (e >= E) return;
    unsigned d = (unsigned)edge_dst(raw, E, e);
    if (d < NODES) atomicAdd(&g_cnt[d], 1);
}

__global__ void dinv_k() {
    int i = blockIdx.x * blockDim.x + threadIdx.x;
    if (i < NODES) g_dinv[i] = rsqrtf(1.0f + (float)g_cnt[i]);
}

__global__ void scan1_k() {
    __shared__ int sh[SCAN_BLK];
    int tid = threadIdx.x;
    int i = blockIdx.x * SCAN_BLK + tid;
    int c = (i < NODES) ? g_cnt[i] : 0;
    sh[tid] = c;
    __syncthreads();
#pragma unroll
    for (int ofs = 1; ofs < SCAN_BLK; ofs <<= 1) {
        int v = (tid >= ofs) ? sh[tid - ofs] : 0;
        __syncthreads();
        sh[tid] += v;
        __syncthreads();
    }
    if (i < NODES) g_rs_local[i] = sh[tid] - c;
    if (tid == SCAN_BLK - 1) g_partial[blockIdx.x] = sh[tid];
}

__global__ void scan2_k() {
    __shared__ int sh[512];
    int tid = threadIdx.x;
    int c = (tid < NBLK) ? g_partial[tid] : 0;
    sh[tid] = c;
    __syncthreads();
#pragma unroll
    for (int ofs = 1; ofs < 512; ofs <<= 1) {
        int v = (tid >= ofs) ? sh[tid - ofs] : 0;
        __syncthreads();
        sh[tid] += v;
        __syncthreads();
    }
    if (tid < NBLK) g_blockoff[tid] = sh[tid] - c;
}

__global__ void scan3_k() {
    int i = blockIdx.x * blockDim.x + threadIdx.x;
    if (i >= NODES) return;
    int rs = g_rs_local[i] + g_blockoff[i / SCAN_BLK];
    g_row_start[i] = rs;
    g_cursor[i]    = rs;
}

__global__ void place_k(const int* __restrict__ raw, int E) {
    int e = blockIdx.x * blockDim.x + threadIdx.x;
    if (e >= E) return;
    unsigned d = (unsigned)edge_dst(raw, E, e);
    unsigned s = (unsigned)edge_src(raw, E, e);
    if (d < NODES && s < NODES) {
        int p = atomicAdd(&g_cursor[d], 1);
        g_eidx[p] = (int)s;
    }
}

// ---------------- tf32 tensor-core GEMM -----------------------------------
// C[M,BN] = A[M,128] @ W[128,BN]; full K resident in smem; 8 warps (4x2),
// warp tile 32 x (BN/2), mma.sync m16n8k8 tf32, fp32 accumulate.
// LAYER2: A := relu(g_a1 + bias[col]), C := g_h2. else: A := x, C := g_h1.
__device__ __forceinline__ uint32_t f2tf32(float f) {
    uint32_t u;
    asm("cvt.rna.tf32.f32 %0, %1;" : "=r"(u) : "f"(f));
    return u;
}

__device__ __forceinline__ void mma_tf32(float d[4], const uint32_t a[4],
                                         uint32_t b0, uint32_t b1) {
    asm volatile(
        "mma.sync.aligned.m16n8k8.row.col.f32.tf32.tf32.f32 "
        "{%0,%1,%2,%3}, {%4,%5,%6,%7}, {%8,%9}, {%0,%1,%2,%3};"
        : "+f"(d[0]), "+f"(d[1]), "+f"(d[2]), "+f"(d[3])
        : "r"(a[0]), "r"(a[1]), "r"(a[2]), "r"(a[3]), "r"(b0), "r"(b1));
}

template <int BN, bool LAYER2>
__global__ void __launch_bounds__(256) mma_gemm_k(
    const float* __restrict__ Ain, const float* __restrict__ W,
    const float* __restrict__ bias, int M)
{
    constexpr int BM = 128, K = 128;
    constexpr int AS = K + 4;     // A smem stride (conflict-free frag reads)
    constexpr int WS = BN + 8;    // W smem stride (conflict-free frag reads)
    constexpr int WN = BN / 2;    // per-warp n extent (warps 4x2)
    constexpr int NT = WN / 8;    // n-tiles per warp

    extern __shared__ uint32_t sh[];
    uint32_t* As = sh;             // [BM][AS]
    uint32_t* Ws = sh + BM * AS;   // [K][WS]

    const float* __restrict__ A = LAYER2 ? (const float*)g_a1 : Ain;
    float* __restrict__ C = LAYER2 ? (float*)g_h2 : (float*)g_h1;

    const int tid = threadIdx.x;
    const int row0 = blockIdx.x * BM;

    // fill A tile (convert to tf32; layer2 fuses relu(a1 + b1))
    for (int i = tid; i < BM * (K / 4); i += 256) {
        int r  = i / (K / 4);
        int c4 = (i % (K / 4)) * 4;
        float4 v = make_float4(0.f, 0.f, 0.f, 0.f);
        if (row0 + r < M)
            v = *(const float4*)(A + (size_t)(row0 + r) * K + c4);
        if (LAYER2) {
            float4 b = *(const float4*)(bias + c4);
            v.x = fmaxf(v.x + b.x, 0.f);
            v.y = fmaxf(v.y + b.y, 0.f);
            v.z = fmaxf(v.z + b.z, 0.f);
            v.w = fmaxf(v.w + b.w, 0.f);
        }
        uint32_t* p = As + r * AS + c4;
        p[0] = f2tf32(v.x); p[1] = f2tf32(v.y);
        p[2] = f2tf32(v.z); p[3] = f2tf32(v.w);
    }
    // fill W tile
    for (int i = tid; i < K * (BN / 4); i += 256) {
        int k  = i / (BN / 4);
        int n4 = (i % (BN / 4)) * 4;
        float4 v = *(const float4*)(W + (size_t)k * BN + n4);
        uint32_t* p = Ws + k * WS + n4;
        p[0] = f2tf32(v.x); p[1] = f2tf32(v.y);
        p[2] = f2tf32(v.z); p[3] = f2tf32(v.w);
    }
    __syncthreads();

    const int lane = tid & 31;
    const int g  = lane >> 2;     // groupID
    const int tg = lane & 3;      // threadID_in_group
    const int wid = tid >> 5;
    const int wm = (wid & 3) * 32;
    const int wn = (wid >> 2) * WN;

    float d[2][NT][4];
#pragma unroll
    for (int mt = 0; mt < 2; mt++)
#pragma unroll
        for (int nt = 0; nt < NT; nt++)
#pragma unroll
            for (int q = 0; q < 4; q++) d[mt][nt][q] = 0.f;

#pragma unroll
    for (int k0 = 0; k0 < K; k0 += 8) {
        uint32_t a[2][4];
#pragma unroll
        for (int mt = 0; mt < 2; mt++) {
            int rb = wm + mt * 16;
            a[mt][0] = As[(rb + g    ) * AS + k0 + tg    ];
            a[mt][1] = As[(rb + g + 8) * AS + k0 + tg    ];
            a[mt][2] = As[(rb + g    ) * AS + k0 + tg + 4];
            a[mt][3] = As[(rb + g + 8) * AS + k0 + tg + 4];
        }
#pragma unroll
        for (int nt = 0; nt < NT; nt++) {
            int n0 = wn + nt * 8;
            uint32_t b0 = Ws[(k0 + tg    ) * WS + n0 + g];
            uint32_t b1 = Ws[(k0 + tg + 4) * WS + n0 + g];
            mma_tf32(d[0][nt], a[0], b0, b1);
            mma_tf32(d[1][nt], a[1], b0, b1);
        }
    }

    // epilogue: c0,c1 -> (row g, cols 2tg,2tg+1); c2,c3 -> row g+8
#pragma unroll
    for (int mt = 0; mt < 2; mt++) {
        int r1 = row0 + wm + mt * 16 + g;
        int r2 = r1 + 8;
#pragma unroll
        for (int nt = 0; nt < NT; nt++) {
            int col = wn + nt * 8 + 2 * tg;
            if (r1 < M)
                *(float2*)(C + (size_t)r1 * BN + col) =
                    make_float2(d[mt][nt][0], d[mt][nt][1]);
            if (r2 < M)
                *(float2*)(C + (size_t)r2 * BN + col) =
                    make_float2(d[mt][nt][2], d[mt][nt][3]);
        }
    }
}

// ---------------- gather aggregation (atomic-free) -------------------------
// layer1: warp per node, lane owns one float4 (128 floats/row).
__global__ void __launch_bounds__(256) agg1_k() {
    int w    = (blockIdx.x * blockDim.x + threadIdx.x) >> 5;
    int lane = threadIdx.x & 31;
    if (w >= NODES) return;

    float dd = g_dinv[w];
    float4 acc = g_h1[(size_t)w * 32 + lane];
    float s2 = dd * dd;
    acc.x *= s2; acc.y *= s2; acc.z *= s2; acc.w *= s2;

    const int n  = g_cnt[w];
    const int rs = g_row_start[w];

    for (int base = 0; base < n; base += 32) {
        int m = n - base; if (m > 32) m = 32;
        int   si = 0; float nd = 0.f;
        if (lane < m) {
            si = g_eidx[rs + base + lane];
            nd = g_dinv[si] * dd;
        }
        for (int j = 0; j < m; j++) {
            int   ss = __shfl_sync(0xffffffffu, si, j);
            float nn = __shfl_sync(0xffffffffu, nd, j);
            float4 v = g_h1[(size_t)ss * 32 + lane];
            acc.x += v.x * nn; acc.y += v.y * nn;
            acc.z += v.z * nn; acc.w += v.w * nn;
        }
    }
    g_a1[(size_t)w * 32 + lane] = acc;
}

// layer2: warp per node, lane owns one float2; fuses bias+relu; writes d_out.
__global__ void __launch_bounds__(256) agg2_k(float2* __restrict__ out,
                                              const float2* __restrict__ b2) {
    int w    = (blockIdx.x * blockDim.x + threadIdx.x) >> 5;
    int lane = threadIdx.x & 31;
    if (w >= NODES) return;

    float dd = g_dinv[w];
    float2 acc = g_h2[(size_t)w * 32 + lane];
    float s2 = dd * dd;
    acc.x *= s2; acc.y *= s2;

    const int n  = g_cnt[w];
    const int rs = g_row_start[w];

    for (int base = 0; base < n; base += 32) {
        int m = n - base; if (m > 32) m = 32;
        int   si = 0; float nd = 0.f;
        if (lane < m) {
            si = g_eidx[rs + base + lane];
            nd = g_dinv[si] * dd;
        }
        for (int j = 0; j < m; j++) {
            int   ss = __shfl_sync(0xffffffffu, si, j);
            float nn = __shfl_sync(0xffffffffu, nd, j);
            float2 v = g_h2[(size_t)ss * 32 + lane];
            acc.x += v.x * nn; acc.y += v.y * nn;
        }
    }
    float2 b = b2[lane];
    acc.x = fmaxf(acc.x + b.x, 0.f);
    acc.y = fmaxf(acc.y + b.y, 0.f);
    out[(size_t)w * 32 + lane] = acc;
}

// ---------------- launch ---------------------------------------------------
extern "C" void kernel_launch(void* const* d_in, const int* in_sizes, int n_in,
                              void* d_out, int out_size) {
    const float* x  = (const float*)d_in[0];
    const void*  ei = d_in[1];
    const float* W1 = (const float*)d_in[2];
    const float* b1 = (const float*)d_in[3];
    const float* W2 = (const float*)d_in[4];
    const float* b2 = (const float*)d_in[5];
    int E = in_sizes[1] / 2;

    for (int i = 0; i < n_in; i++) {
        switch (in_sizes[i]) {
            case NODES * KIN: x  = (const float*)d_in[i]; break;
            case 2 * EMAX:    ei = d_in[i]; E = in_sizes[i] / 2; break;
            case KIN * 128:   W1 = (const float*)d_in[i]; break;
            case 128:         b1 = (const float*)d_in[i]; break;
            case 128 * 64:    W2 = (const float*)d_in[i]; break;
            case 64:          b2 = (const float*)d_in[i]; break;
            default: break;
        }
    }
    if (E > EMAX) E = EMAX;

    const int M = NODES;
    const int gemm_blocks = (M + 127) / 128;
    const int node_blocks = (NODES + 255) / 256;
    const int edge_blocks = (E + 255) / 256;
    const int warp_blocks = (NODES * 32 + 255) / 256;

    // dynamic smem: (128*(128+4) + 128*(BN+8)) * 4 bytes
    const int smem1 = (128 * 132 + 128 * 136) * 4;  // 137216
    const int smem2 = (128 * 132 + 128 * 72)  * 4;  // 104448
    cudaFuncSetAttribute(mma_gemm_k<128, false>,
                         cudaFuncAttributeMaxDynamicSharedMemorySize, smem1);
    cudaFuncSetAttribute(mma_gemm_k<64, true>,
                         cudaFuncAttributeMaxDynamicSharedMemorySize, smem2);

    detect_k   <<<1, 32>>>((const int*)ei);
    cnt_init_k <<<node_blocks, 256>>>();
    cnt_count_k<<<edge_blocks, 256>>>((const int*)ei, E);
    dinv_k     <<<node_blocks, 256>>>();
    scan1_k    <<<NBLK, SCAN_BLK>>>();
    scan2_k    <<<1, 512>>>();
    scan3_k    <<<node_blocks, 256>>>();
    place_k    <<<edge_blocks, 256>>>((const int*)ei, E);

    mma_gemm_k<128, false><<<gemm_blocks, 256, smem1>>>(x, W1, nullptr, M);
    agg1_k<<<warp_blocks, 256>>>();

    mma_gemm_k<64, true><<<gemm_blocks, 256, smem2>>>(nullptr, W2, b1, M);
    agg2_k<<<warp_blocks, 256>>>((float2*)d_out, (const float2*)b2);
}

// round 8
// speedup vs baseline: 1.4128x; 1.3236x over previous
#include <cuda_runtime.h>
#include <cstdint>

// 2-layer GCN, atomic-free aggregation via device-built CSR.
// GEMMs on tensor cores (mma.sync tf32, fp32 accumulate), K-chunked for
// 2 CTAs/SM. h = relu(Anorm(x@W1)+b1); out = relu(Anorm(h@W2)+b2)

#define NODES 100000
#define EMAX  1600000
#define KIN   128
#define SCAN_BLK 256
#define NBLK ((NODES + SCAN_BLK - 1) / SCAN_BLK)   // 391

// ---------------- device scratch ------------------------------------------
__device__ int    g_is64;
__device__ int    g_cnt[NODES];        // in-degree (excl self-loop)
__device__ int    g_rs_local[NODES];
__device__ int    g_partial[NBLK];
__device__ int    g_blockoff[NBLK];
__device__ int    g_row_start[NODES];
__device__ int    g_cursor[NODES];
__device__ int    g_eidx[EMAX];        // CSR: src indices grouped by dst
__device__ float  g_dinv[NODES];
__device__ float4 g_h1[(size_t)NODES * 32];  // x @ W1            [N,128]
__device__ float4 g_a1[(size_t)NODES * 32];  // aggregated layer1 [N,128]
__device__ float2 g_h2[(size_t)NODES * 32];  // relu(a1+b1) @ W2  [N,64]

// ---------------- init + edge dtype detect (fused) --------------------------
// int64 little-endian with values < 100000 => every odd 32-bit word is 0.
__global__ void init_detect_k(const int* __restrict__ raw) {
    int i = blockIdx.x * blockDim.x + threadIdx.x;
    if (i < NODES) g_cnt[i] = 0;
    if (blockIdx.x == 0 && threadIdx.x < 32) {
        int zc = 0;
        for (int j = threadIdx.x; j < 1024; j += 32)
            if (raw[2 * j + 1] == 0) zc++;
#pragma unroll
        for (int o = 16; o > 0; o >>= 1)
            zc += __shfl_down_sync(0xffffffffu, zc, o);
        if (threadIdx.x == 0) g_is64 = (zc > 512) ? 1 : 0;
    }
}

__device__ __forceinline__ int edge_src(const int* raw, int E, int e) {
    return g_is64 ? raw[2 * e] : raw[e];
}
__device__ __forceinline__ int edge_dst(const int* raw, int E, int e) {
    return g_is64 ? raw[2 * (E + e)] : raw[E + e];
}

// ---------------- CSR build ------------------------------------------------
__global__ void cnt_count_k(const int* __restrict__ raw, int E) {
    int e = blockIdx.x * blockDim.x + threadIdx.x;
    if (e >= E) return;
    unsigned d = (unsigned)edge_dst(raw, E, e);
    if (d < NODES) atomicAdd(&g_cnt[d], 1);
}

// pass 1: per-block scan (+ fused dinv compute)
__global__ void scan1_k() {
    __shared__ int sh[SCAN_BLK];
    int tid = threadIdx.x;
    int i = blockIdx.x * SCAN_BLK + tid;
    int c = (i < NODES) ? g_cnt[i] : 0;
    if (i < NODES) g_dinv[i] = rsqrtf(1.0f + (float)c);
    sh[tid] = c;
    __syncthreads();
#pragma unroll
    for (int ofs = 1; ofs < SCAN_BLK; ofs <<= 1) {
        int v = (tid >= ofs) ? sh[tid - ofs] : 0;
        __syncthreads();
        sh[tid] += v;
        __syncthreads();
    }
    if (i < NODES) g_rs_local[i] = sh[tid] - c;
    if (tid == SCAN_BLK - 1) g_partial[blockIdx.x] = sh[tid];
}

__global__ void scan2_k() {
    __shared__ int sh[512];
    int tid = threadIdx.x;
    int c = (tid < NBLK) ? g_partial[tid] : 0;
    sh[tid] = c;
    __syncthreads();
#pragma unroll
    for (int ofs = 1; ofs < 512; ofs <<= 1) {
        int v = (tid >= ofs) ? sh[tid - ofs] : 0;
        __syncthreads();
        sh[tid] += v;
        __syncthreads();
    }
    if (tid < NBLK) g_blockoff[tid] = sh[tid] - c;
}

__global__ void scan3_k() {
    int i = blockIdx.x * blockDim.x + threadIdx.x;
    if (i >= NODES) return;
    int rs = g_rs_local[i] + g_blockoff[i / SCAN_BLK];
    g_row_start[i] = rs;
    g_cursor[i]    = rs;
}

__global__ void place_k(const int* __restrict__ raw, int E) {
    int e = blockIdx.x * blockDim.x + threadIdx.x;
    if (e >= E) return;
    unsigned d = (unsigned)edge_dst(raw, E, e);
    unsigned s = (unsigned)edge_src(raw, E, e);
    if (d < NODES && s < NODES) {
        int p = atomicAdd(&g_cursor[d], 1);
        g_eidx[p] = (int)s;
    }
}

// ---------------- tf32 tensor-core GEMM (K-chunked, 2 CTAs/SM) -------------
// C[M,BN] = A[M,128] @ W[128,BN]; K in 2 chunks of 64 through one smem
// buffer; 8 warps (4x2), warp tile 32 x (BN/2), mma m16n8k8 tf32.
// LAYER2: A := relu(g_a1 + bias[col]), C := g_h2. else: A := x, C := g_h1.
__device__ __forceinline__ uint32_t f2tf32(float f) {
    uint32_t u;
    asm("cvt.rna.tf32.f32 %0, %1;" : "=r"(u) : "f"(f));
    return u;
}

__device__ __forceinline__ void mma_tf32(float d[4], const uint32_t a[4],
                                         uint32_t b0, uint32_t b1) {
    asm volatile(
        "mma.sync.aligned.m16n8k8.row.col.f32.tf32.tf32.f32 "
        "{%0,%1,%2,%3}, {%4,%5,%6,%7}, {%8,%9}, {%0,%1,%2,%3};"
        : "+f"(d[0]), "+f"(d[1]), "+f"(d[2]), "+f"(d[3])
        : "r"(a[0]), "r"(a[1]), "r"(a[2]), "r"(a[3]), "r"(b0), "r"(b1));
}

template <int BN, bool LAYER2>
__global__ void __launch_bounds__(256) mma_gemm_k(
    const float* __restrict__ Ain, const float* __restrict__ W,
    const float* __restrict__ bias, int M)
{
    constexpr int BM = 128, K = 128, KC = 64;
    constexpr int AS = KC + 4;    // A smem stride (68): frag banks 4g+tg ok
    constexpr int WS = BN + 8;    // W smem stride: frag banks 8tg+g ok
    constexpr int WN = BN / 2;    // per-warp n extent (warps 4x2)
    constexpr int NT = WN / 8;

    extern __shared__ uint32_t sh[];
    uint32_t* As = sh;             // [BM][AS]
    uint32_t* Ws = sh + BM * AS;   // [KC][WS]

    const float* __restrict__ A = LAYER2 ? (const float*)g_a1 : Ain;
    float* __restrict__ C = LAYER2 ? (float*)g_h2 : (float*)g_h1;

    const int tid = threadIdx.x;
    const int row0 = blockIdx.x * BM;

    const int lane = tid & 31;
    const int g  = lane >> 2;
    const int tg = lane & 3;
    const int wid = tid >> 5;
    const int wm = (wid & 3) * 32;
    const int wn = (wid >> 2) * WN;

    float d[2][NT][4];
#pragma unroll
    for (int mt = 0; mt < 2; mt++)
#pragma unroll
        for (int nt = 0; nt < NT; nt++)
#pragma unroll
            for (int q = 0; q < 4; q++) d[mt][nt][q] = 0.f;

#pragma unroll
    for (int kc = 0; kc < K / KC; kc++) {
        if (kc) __syncthreads();   // all warps done with previous chunk

        // fill A chunk [128][64] (tf32; layer2 fuses relu(a1 + b1))
        for (int i = tid; i < BM * (KC / 4); i += 256) {
            int r  = i / (KC / 4);
            int c4 = (i % (KC / 4)) * 4;
            float4 v = make_float4(0.f, 0.f, 0.f, 0.f);
            if (row0 + r < M)
                v = *(const float4*)(A + (size_t)(row0 + r) * K + kc * KC + c4);
            if (LAYER2) {
                float4 b = *(const float4*)(bias + kc * KC + c4);
                v.x = fmaxf(v.x + b.x, 0.f);
                v.y = fmaxf(v.y + b.y, 0.f);
                v.z = fmaxf(v.z + b.z, 0.f);
                v.w = fmaxf(v.w + b.w, 0.f);
            }
            uint32_t* p = As + r * AS + c4;
            p[0] = f2tf32(v.x); p[1] = f2tf32(v.y);
            p[2] = f2tf32(v.z); p[3] = f2tf32(v.w);
        }
        // fill W chunk [64][BN]
        for (int i = tid; i < KC * (BN / 4); i += 256) {
            int k  = i / (BN / 4);
            int n4 = (i % (BN / 4)) * 4;
            float4 v = *(const float4*)(W + (size_t)(kc * KC + k) * BN + n4);
            uint32_t* p = Ws + k * WS + n4;
            p[0] = f2tf32(v.x); p[1] = f2tf32(v.y);
            p[2] = f2tf32(v.z); p[3] = f2tf32(v.w);
        }
        __syncthreads();

#pragma unroll
        for (int k0 = 0; k0 < KC; k0 += 8) {
            uint32_t a[2][4];
#pragma unroll
            for (int mt = 0; mt < 2; mt++) {
                int rb = wm + mt * 16;
                a[mt][0] = As[(rb + g    ) * AS + k0 + tg    ];
                a[mt][1] = As[(rb + g + 8) * AS + k0 + tg    ];
                a[mt][2] = As[(rb + g    ) * AS + k0 + tg + 4];
                a[mt][3] = As[(rb + g + 8) * AS + k0 + tg + 4];
            }
#pragma unroll
            for (int nt = 0; nt < NT; nt++) {
                int n0 = wn + nt * 8;
                uint32_t b0 = Ws[(k0 + tg    ) * WS + n0 + g];
                uint32_t b1 = Ws[(k0 + tg + 4) * WS + n0 + g];
                mma_tf32(d[0][nt], a[0], b0, b1);
                mma_tf32(d[1][nt], a[1], b0, b1);
            }
        }
    }

    // epilogue: c0,c1 -> (row g, cols 2tg,2tg+1); c2,c3 -> row g+8
#pragma unroll
    for (int mt = 0; mt < 2; mt++) {
        int r1 = row0 + wm + mt * 16 + g;
        int r2 = r1 + 8;
#pragma unroll
        for (int nt = 0; nt < NT; nt++) {
            int col = wn + nt * 8 + 2 * tg;
            if (r1 < M)
                *(float2*)(C + (size_t)r1 * BN + col) =
                    make_float2(d[mt][nt][0], d[mt][nt][1]);
            if (r2 < M)
                *(float2*)(C + (size_t)r2 * BN + col) =
                    make_float2(d[mt][nt][2], d[mt][nt][3]);
        }
    }
}

// ---------------- gather aggregation (atomic-free) -------------------------
// Warp per node; uniform loads of eidx/dinv (single request/warp, L1-cached),
// unrolled x2 for independent load chains.
__global__ void __launch_bounds__(256) agg1_k() {
    int w    = (blockIdx.x * blockDim.x + threadIdx.x) >> 5;
    int lane = threadIdx.x & 31;
    if (w >= NODES) return;

    float dd = g_dinv[w];
    float4 acc = g_h1[(size_t)w * 32 + lane];
    float s2 = dd * dd;
    acc.x *= s2; acc.y *= s2; acc.z *= s2; acc.w *= s2;

    const int n  = g_cnt[w];
    const int rs = g_row_start[w];

    int j = 0;
    for (; j + 2 <= n; j += 2) {
        int s0 = g_eidx[rs + j];
        int s1 = g_eidx[rs + j + 1];
        float n0 = g_dinv[s0] * dd;
        float n1 = g_dinv[s1] * dd;
        float4 v0 = g_h1[(size_t)s0 * 32 + lane];
        float4 v1 = g_h1[(size_t)s1 * 32 + lane];
        acc.x += v0.x * n0 + v1.x * n1;
        acc.y += v0.y * n0 + v1.y * n1;
        acc.z += v0.z * n0 + v1.z * n1;
        acc.w += v0.w * n0 + v1.w * n1;
    }
    if (j < n) {
        int s0 = g_eidx[rs + j];
        float n0 = g_dinv[s0] * dd;
        float4 v0 = g_h1[(size_t)s0 * 32 + lane];
        acc.x += v0.x * n0; acc.y += v0.y * n0;
        acc.z += v0.z * n0; acc.w += v0.w * n0;
    }
    g_a1[(size_t)w * 32 + lane] = acc;
}

// layer2: lane owns one float2; fuses bias+relu; writes d_out directly.
__global__ void __launch_bounds__(256) agg2_k(float2* __restrict__ out,
                                              const float2* __restrict__ b2) {
    int w    = (blockIdx.x * blockDim.x + threadIdx.x) >> 5;
    int lane = threadIdx.x & 31;
    if (w >= NODES) return;

    float dd = g_dinv[w];
    float2 acc = g_h2[(size_t)w * 32 + lane];
    float s2 = dd * dd;
    acc.x *= s2; acc.y *= s2;

    const int n  = g_cnt[w];
    const int rs = g_row_start[w];

    int j = 0;
    for (; j + 2 <= n; j += 2) {
        int s0 = g_eidx[rs + j];
        int s1 = g_eidx[rs + j + 1];
        float n0 = g_dinv[s0] * dd;
        float n1 = g_dinv[s1] * dd;
        float2 v0 = g_h2[(size_t)s0 * 32 + lane];
        float2 v1 = g_h2[(size_t)s1 * 32 + lane];
        acc.x += v0.x * n0 + v1.x * n1;
        acc.y += v0.y * n0 + v1.y * n1;
    }
    if (j < n) {
        int s0 = g_eidx[rs + j];
        float n0 = g_dinv[s0] * dd;
        float2 v0 = g_h2[(size_t)s0 * 32 + lane];
        acc.x += v0.x * n0; acc.y += v0.y * n0;
    }
    float2 b = b2[lane];
    acc.x = fmaxf(acc.x + b.x, 0.f);
    acc.y = fmaxf(acc.y + b.y, 0.f);
    out[(size_t)w * 32 + lane] = acc;
}

// ---------------- launch ---------------------------------------------------
extern "C" void kernel_launch(void* const* d_in, const int* in_sizes, int n_in,
                              void* d_out, int out_size) {
    const float* x  = (const float*)d_in[0];
    const void*  ei = d_in[1];
    const float* W1 = (const float*)d_in[2];
    const float* b1 = (const float*)d_in[3];
    const float* W2 = (const float*)d_in[4];
    const float* b2 = (const float*)d_in[5];
    int E = in_sizes[1] / 2;

    for (int i = 0; i < n_in; i++) {
        switch (in_sizes[i]) {
            case NODES * KIN: x  = (const float*)d_in[i]; break;
            case 2 * EMAX:    ei = d_in[i]; E = in_sizes[i] / 2; break;
            case KIN * 128:   W1 = (const float*)d_in[i]; break;
            case 128:         b1 = (const float*)d_in[i]; break;
            case 128 * 64:    W2 = (const float*)d_in[i]; break;
            case 64:          b2 = (const float*)d_in[i]; break;
            default: break;
        }
    }
    if (E > EMAX) E = EMAX;

    const int M = NODES;
    const int gemm_blocks = (M + 127) / 128;
    const int node_blocks = (NODES + 255) / 256;
    const int edge_blocks = (E + 255) / 256;
    const int warp_blocks = (NODES * 32 + 255) / 256;

    // dynamic smem: (128*68 + 64*(BN+8)) * 4 bytes  -> 2 CTAs/SM
    const int smem1 = (128 * 68 + 64 * 136) * 4;  // 69632
    const int smem2 = (128 * 68 + 64 * 72)  * 4;  // 53248
    cudaFuncSetAttribute(mma_gemm_k<128, false>,
                         cudaFuncAttributeMaxDynamicSharedMemorySize, smem1);
    cudaFuncSetAttribute(mma_gemm_k<64, true>,
                         cudaFuncAttributeMaxDynamicSharedMemorySize, smem2);

    init_detect_k<<<node_blocks, 256>>>((const int*)ei);
    cnt_count_k  <<<edge_blocks, 256>>>((const int*)ei, E);
    scan1_k      <<<NBLK, SCAN_BLK>>>();
    scan2_k      <<<1, 512>>>();
    scan3_k      <<<node_blocks, 256>>>();
    place_k      <<<edge_blocks, 256>>>((const int*)ei, E);

    mma_gemm_k<128, false><<<gemm_blocks, 256, smem1>>>(x, W1, nullptr, M);
    agg1_k<<<warp_blocks, 256>>>();

    mma_gemm_k<64, true><<<gemm_blocks, 256, smem2>>>(nullptr, W2, b1, M);
    agg2_k<<<warp_blocks, 256>>>((float2*)d_out, (const float2*)b2);
}

// round 9
// speedup vs baseline: 1.5989x; 1.1317x over previous
#include <cuda_runtime.h>
#include <cuda_fp16.h>
#include <cstdint>

// 2-layer GCN, atomic-free aggregation via device-built CSR.
// GEMMs on tensor cores (tf32, fp32 accumulate, 2 CTAs/SM); hidden features
// stored fp16 to halve gather traffic (accumulation stays fp32).
// h = relu(Anorm(x@W1)+b1); out = relu(Anorm(h@W2)+b2)

#define NODES 100000
#define EMAX  1600000
#define KIN   128
#define SCAN_BLK 256
#define NBLK ((NODES + SCAN_BLK - 1) / SCAN_BLK)   // 391

// ---------------- device scratch ------------------------------------------
__device__ int     g_is64;
__device__ int     g_cnt[NODES];       // in-degree (excl self-loop)
__device__ int     g_rs_local[NODES];
__device__ int     g_partial[NBLK];
__device__ int     g_blockoff[NBLK];
__device__ int     g_row_start[NODES];
__device__ int     g_cursor[NODES];
__device__ int     g_eidx[EMAX];       // CSR: src indices grouped by dst
__device__ float   g_dinv[NODES];
__device__ __half2 g_h1h[(size_t)NODES * 64];  // x @ W1 (fp16)      [N,128]
__device__ float4  g_a1[(size_t)NODES * 32];   // aggregated layer1  [N,128]
__device__ __half2 g_h2h[(size_t)NODES * 32];  // relu(a1+b1)@W2 (fp16) [N,64]

// ---------------- init + edge dtype detect (fused) --------------------------
__global__ void init_detect_k(const int* __restrict__ raw) {
    int i = blockIdx.x * blockDim.x + threadIdx.x;
    if (i < NODES) g_cnt[i] = 0;
    if (blockIdx.x == 0 && threadIdx.x < 32) {
        int zc = 0;
        for (int j = threadIdx.x; j < 1024; j += 32)
            if (raw[2 * j + 1] == 0) zc++;
#pragma unroll
        for (int o = 16; o > 0; o >>= 1)
            zc += __shfl_down_sync(0xffffffffu, zc, o);
        if (threadIdx.x == 0) g_is64 = (zc > 512) ? 1 : 0;
    }
}

__device__ __forceinline__ int edge_src(const int* raw, int E, int e) {
    return g_is64 ? raw[2 * e] : raw[e];
}
__device__ __forceinline__ int edge_dst(const int* raw, int E, int e) {
    return g_is64 ? raw[2 * (E + e)] : raw[E + e];
}

// ---------------- CSR build ------------------------------------------------
__global__ void cnt_count_k(const int* __restrict__ raw, int E) {
    int e = blockIdx.x * blockDim.x + threadIdx.x;
    if (e >= E) return;
    unsigned d = (unsigned)edge_dst(raw, E, e);
    if (d < NODES) atomicAdd(&g_cnt[d], 1);
}

// pass 1: per-block scan (+ fused dinv compute)
__global__ void scan1_k() {
    __shared__ int sh[SCAN_BLK];
    int tid = threadIdx.x;
    int i = blockIdx.x * SCAN_BLK + tid;
    int c = (i < NODES) ? g_cnt[i] : 0;
    if (i < NODES) g_dinv[i] = rsqrtf(1.0f + (float)c);
    sh[tid] = c;
    __syncthreads();
#pragma unroll
    for (int ofs = 1; ofs < SCAN_BLK; ofs <<= 1) {
        int v = (tid >= ofs) ? sh[tid - ofs] : 0;
        __syncthreads();
        sh[tid] += v;
        __syncthreads();
    }
    if (i < NODES) g_rs_local[i] = sh[tid] - c;
    if (tid == SCAN_BLK - 1) g_partial[blockIdx.x] = sh[tid];
}

__global__ void scan2_k() {
    __shared__ int sh[512];
    int tid = threadIdx.x;
    int c = (tid < NBLK) ? g_partial[tid] : 0;
    sh[tid] = c;
    __syncthreads();
#pragma unroll
    for (int ofs = 1; ofs < 512; ofs <<= 1) {
        int v = (tid >= ofs) ? sh[tid - ofs] : 0;
        __syncthreads();
        sh[tid] += v;
        __syncthreads();
    }
    if (tid < NBLK) g_blockoff[tid] = sh[tid] - c;
}

__global__ void scan3_k() {
    int i = blockIdx.x * blockDim.x + threadIdx.x;
    if (i >= NODES) return;
    int rs = g_rs_local[i] + g_blockoff[i / SCAN_BLK];
    g_row_start[i] = rs;
    g_cursor[i]    = rs;
}

__global__ void place_k(const int* __restrict__ raw, int E) {
    int e = blockIdx.x * blockDim.x + threadIdx.x;
    if (e >= E) return;
    unsigned d = (unsigned)edge_dst(raw, E, e);
    unsigned s = (unsigned)edge_src(raw, E, e);
    if (d < NODES && s < NODES) {
        int p = atomicAdd(&g_cursor[d], 1);
        g_eidx[p] = (int)s;
    }
}

// ---------------- tf32 tensor-core GEMM (K-chunked, 2 CTAs/SM) -------------
// C[M,BN] = A[M,128] @ W[128,BN]; fp16 output (g_h1h / g_h2h).
// LAYER2: A := relu(g_a1 + bias[col]). else: A := x.
__device__ __forceinline__ uint32_t f2tf32(float f) {
    uint32_t u;
    asm("cvt.rna.tf32.f32 %0, %1;" : "=r"(u) : "f"(f));
    return u;
}

__device__ __forceinline__ void mma_tf32(float d[4], const uint32_t a[4],
                                         uint32_t b0, uint32_t b1) {
    asm volatile(
        "mma.sync.aligned.m16n8k8.row.col.f32.tf32.tf32.f32 "
        "{%0,%1,%2,%3}, {%4,%5,%6,%7}, {%8,%9}, {%0,%1,%2,%3};"
        : "+f"(d[0]), "+f"(d[1]), "+f"(d[2]), "+f"(d[3])
        : "r"(a[0]), "r"(a[1]), "r"(a[2]), "r"(a[3]), "r"(b0), "r"(b1));
}

template <int BN, bool LAYER2>
__global__ void __launch_bounds__(256) mma_gemm_k(
    const float* __restrict__ Ain, const float* __restrict__ W,
    const float* __restrict__ bias, int M)
{
    constexpr int BM = 128, K = 128, KC = 64;
    constexpr int AS = KC + 4;    // A smem stride (68)
    constexpr int WS = BN + 8;    // W smem stride
    constexpr int WN = BN / 2;    // per-warp n extent (warps 4x2)
    constexpr int NT = WN / 8;

    extern __shared__ uint32_t sh[];
    uint32_t* As = sh;             // [BM][AS]
    uint32_t* Ws = sh + BM * AS;   // [KC][WS]

    const float* __restrict__ A = LAYER2 ? (const float*)g_a1 : Ain;
    __half2* __restrict__ Ch = LAYER2 ? g_h2h : g_h1h;

    const int tid = threadIdx.x;
    const int row0 = blockIdx.x * BM;

    const int lane = tid & 31;
    const int g  = lane >> 2;
    const int tg = lane & 3;
    const int wid = tid >> 5;
    const int wm = (wid & 3) * 32;
    const int wn = (wid >> 2) * WN;

    float d[2][NT][4];
#pragma unroll
    for (int mt = 0; mt < 2; mt++)
#pragma unroll
        for (int nt = 0; nt < NT; nt++)
#pragma unroll
            for (int q = 0; q < 4; q++) d[mt][nt][q] = 0.f;

#pragma unroll
    for (int kc = 0; kc < K / KC; kc++) {
        if (kc) __syncthreads();

        // fill A chunk [128][64] (tf32; layer2 fuses relu(a1 + b1))
        for (int i = tid; i < BM * (KC / 4); i += 256) {
            int r  = i / (KC / 4);
            int c4 = (i % (KC / 4)) * 4;
            float4 v = make_float4(0.f, 0.f, 0.f, 0.f);
            if (row0 + r < M)
                v = *(const float4*)(A + (size_t)(row0 + r) * K + kc * KC + c4);
            if (LAYER2) {
                float4 b = *(const float4*)(bias + kc * KC + c4);
                v.x = fmaxf(v.x + b.x, 0.f);
                v.y = fmaxf(v.y + b.y, 0.f);
                v.z = fmaxf(v.z + b.z, 0.f);
                v.w = fmaxf(v.w + b.w, 0.f);
            }
            uint32_t* p = As + r * AS + c4;
            p[0] = f2tf32(v.x); p[1] = f2tf32(v.y);
            p[2] = f2tf32(v.z); p[3] = f2tf32(v.w);
        }
        // fill W chunk [64][BN]
        for (int i = tid; i < KC * (BN / 4); i += 256) {
            int k  = i / (BN / 4);
            int n4 = (i % (BN / 4)) * 4;
            float4 v = *(const float4*)(W + (size_t)(kc * KC + k) * BN + n4);
            uint32_t* p = Ws + k * WS + n4;
            p[0] = f2tf32(v.x); p[1] = f2tf32(v.y);
            p[2] = f2tf32(v.z); p[3] = f2tf32(v.w);
        }
        __syncthreads();

#pragma unroll
        for (int k0 = 0; k0 < KC; k0 += 8) {
            uint32_t a[2][4];
#pragma unroll
            for (int mt = 0; mt < 2; mt++) {
                int rb = wm + mt * 16;
                a[mt][0] = As[(rb + g    ) * AS + k0 + tg    ];
                a[mt][1] = As[(rb + g + 8) * AS + k0 + tg    ];
                a[mt][2] = As[(rb + g    ) * AS + k0 + tg + 4];
                a[mt][3] = As[(rb + g + 8) * AS + k0 + tg + 4];
            }
#pragma unroll
            for (int nt = 0; nt < NT; nt++) {
                int n0 = wn + nt * 8;
                uint32_t b0 = Ws[(k0 + tg    ) * WS + n0 + g];
                uint32_t b1 = Ws[(k0 + tg + 4) * WS + n0 + g];
                mma_tf32(d[0][nt], a[0], b0, b1);
                mma_tf32(d[1][nt], a[1], b0, b1);
            }
        }
    }

    // epilogue: one __half2 per fragment pair (cols 2tg, 2tg+1 adjacent)
    constexpr int RH = BN / 2;  // half2 per row
#pragma unroll
    for (int mt = 0; mt < 2; mt++) {
        int r1 = row0 + wm + mt * 16 + g;
        int r2 = r1 + 8;
#pragma unroll
        for (int nt = 0; nt < NT; nt++) {
            int ch = (wn + nt * 8 + 2 * tg) / 2;
            if (r1 < M)
                Ch[(size_t)r1 * RH + ch] =
                    __floats2half2_rn(d[mt][nt][0], d[mt][nt][1]);
            if (r2 < M)
                Ch[(size_t)r2 * RH + ch] =
                    __floats2half2_rn(d[mt][nt][2], d[mt][nt][3]);
        }
    }
}

// ---------------- gather aggregation (atomic-free, fp16 gathers) -----------
// layer1: warp per node; lane owns 4 cols (one uint2 = 2 half2 = 8B).
__global__ void __launch_bounds__(256) agg1_k() {
    int w    = (blockIdx.x * blockDim.x + threadIdx.x) >> 5;
    int lane = threadIdx.x & 31;
    if (w >= NODES) return;

    const uint2* __restrict__ H = (const uint2*)g_h1h;  // [N][32] uint2

    float dd = g_dinv[w];
    float s2 = dd * dd;
    float4 acc;
    {
        uint2 raw = H[(size_t)w * 32 + lane];
        float2 f0 = __half22float2(*reinterpret_cast<__half2*>(&raw.x));
        float2 f1 = __half22float2(*reinterpret_cast<__half2*>(&raw.y));
        acc = make_float4(f0.x * s2, f0.y * s2, f1.x * s2, f1.y * s2);
    }

    const int n  = g_cnt[w];
    const int rs = g_row_start[w];

    int j = 0;
    for (; j + 2 <= n; j += 2) {
        int s0 = g_eidx[rs + j];
        int s1 = g_eidx[rs + j + 1];
        float n0 = g_dinv[s0] * dd;
        float n1 = g_dinv[s1] * dd;
        uint2 r0 = H[(size_t)s0 * 32 + lane];
        uint2 r1 = H[(size_t)s1 * 32 + lane];
        float2 a0 = __half22float2(*reinterpret_cast<__half2*>(&r0.x));
        float2 b0 = __half22float2(*reinterpret_cast<__half2*>(&r0.y));
        float2 a1 = __half22float2(*reinterpret_cast<__half2*>(&r1.x));
        float2 b1 = __half22float2(*reinterpret_cast<__half2*>(&r1.y));
        acc.x += a0.x * n0 + a1.x * n1;
        acc.y += a0.y * n0 + a1.y * n1;
        acc.z += b0.x * n0 + b1.x * n1;
        acc.w += b0.y * n0 + b1.y * n1;
    }
    if (j < n) {
        int s0 = g_eidx[rs + j];
        float n0 = g_dinv[s0] * dd;
        uint2 r0 = H[(size_t)s0 * 32 + lane];
        float2 a0 = __half22float2(*reinterpret_cast<__half2*>(&r0.x));
        float2 b0 = __half22float2(*reinterpret_cast<__half2*>(&r0.y));
        acc.x += a0.x * n0; acc.y += a0.y * n0;
        acc.z += b0.x * n0; acc.w += b0.y * n0;
    }
    g_a1[(size_t)w * 32 + lane] = acc;
}

// layer2: lane owns one half2 (2 cols); fuses bias+relu; writes d_out fp32.
__global__ void __launch_bounds__(256) agg2_k(float2* __restrict__ out,
                                              const float2* __restrict__ b2) {
    int w    = (blockIdx.x * blockDim.x + threadIdx.x) >> 5;
    int lane = threadIdx.x & 31;
    if (w >= NODES) return;

    float dd = g_dinv[w];
    float s2 = dd * dd;
    float2 acc;
    {
        float2 f = __half22float2(g_h2h[(size_t)w * 32 + lane]);
        acc = make_float2(f.x * s2, f.y * s2);
    }

    const int n  = g_cnt[w];
    const int rs = g_row_start[w];

    int j = 0;
    for (; j + 2 <= n; j += 2) {
        int s0 = g_eidx[rs + j];
        int s1 = g_eidx[rs + j + 1];
        float n0 = g_dinv[s0] * dd;
        float n1 = g_dinv[s1] * dd;
        float2 v0 = __half22float2(g_h2h[(size_t)s0 * 32 + lane]);
        float2 v1 = __half22float2(g_h2h[(size_t)s1 * 32 + lane]);
        acc.x += v0.x * n0 + v1.x * n1;
        acc.y += v0.y * n0 + v1.y * n1;
    }
    if (j < n) {
        int s0 = g_eidx[rs + j];
        float n0 = g_dinv[s0] * dd;
        float2 v0 = __half22float2(g_h2h[(size_t)s0 * 32 + lane]);
        acc.x += v0.x * n0; acc.y += v0.y * n0;
    }
    float2 b = b2[lane];
    acc.x = fmaxf(acc.x + b.x, 0.f);
    acc.y = fmaxf(acc.y + b.y, 0.f);
    out[(size_t)w * 32 + lane] = acc;
}

// ---------------- launch ---------------------------------------------------
extern "C" void kernel_launch(void* const* d_in, const int* in_sizes, int n_in,
                              void* d_out, int out_size) {
    const float* x  = (const float*)d_in[0];
    const void*  ei = d_in[1];
    const float* W1 = (const float*)d_in[2];
    const float* b1 = (const float*)d_in[3];
    const float* W2 = (const float*)d_in[4];
    const float* b2 = (const float*)d_in[5];
    int E = in_sizes[1] / 2;

    for (int i = 0; i < n_in; i++) {
        switch (in_sizes[i]) {
            case NODES * KIN: x  = (const float*)d_in[i]; break;
            case 2 * EMAX:    ei = d_in[i]; E = in_sizes[i] / 2; break;
            case KIN * 128:   W1 = (const float*)d_in[i]; break;
            case 128:         b1 = (const float*)d_in[i]; break;
            case 128 * 64:    W2 = (const float*)d_in[i]; break;
            case 64:          b2 = (const float*)d_in[i]; break;
            default: break;
        }
    }
    if (E > EMAX) E = EMAX;

    const int M = NODES;
    const int gemm_blocks = (M + 127) / 128;
    const int node_blocks = (NODES + 255) / 256;
    const int edge_blocks = (E + 255) / 256;
    const int warp_blocks = (NODES * 32 + 255) / 256;

    // dynamic smem: (128*68 + 64*(BN+8)) * 4 bytes -> 2 CTAs/SM
    const int smem1 = (128 * 68 + 64 * 136) * 4;  // 69632
    const int smem2 = (128 * 68 + 64 * 72)  * 4;  // 53248
    cudaFuncSetAttribute(mma_gemm_k<128, false>,
                         cudaFuncAttributeMaxDynamicSharedMemorySize, smem1);
    cudaFuncSetAttribute(mma_gemm_k<64, true>,
                         cudaFuncAttributeMaxDynamicSharedMemorySize, smem2);

    init_detect_k<<<node_blocks, 256>>>((const int*)ei);
    cnt_count_k  <<<edge_blocks, 256>>>((const int*)ei, E);
    scan1_k      <<<NBLK, SCAN_BLK>>>();
    scan2_k      <<<1, 512>>>();
    scan3_k      <<<node_blocks, 256>>>();
    place_k      <<<edge_blocks, 256>>>((const int*)ei, E);

    mma_gemm_k<128, false><<<gemm_blocks, 256, smem1>>>(x, W1, nullptr, M);
    agg1_k<<<warp_blocks, 256>>>();

    mma_gemm_k<64, true><<<gemm_blocks, 256, smem2>>>(nullptr, W2, b1, M);
    agg2_k<<<warp_blocks, 256>>>((float2*)d_out, (const float2*)b2);
}